// round 13
// baseline (speedup 1.0000x reference)
#include <cuda_runtime.h>
#include <cuda_fp16.h>
#include <math.h>
#include <stdint.h>

#define CB 2
#define CT 1024
#define CD 256
#define CH 4
#define CNH 8192
#define CN 32768
#define CV 256
#define CL 6
#define FH 4096
#define EPSV 1e-5f

// narrow GEMM smem: 4 arrays x 128 rows x 64B (KC=32), XOR-swizzled
#define ARR_BYTES (128*64)             // 8192
#define STAGE_BYTES (4*ARR_BYTES)      // 32768
#define NSTAGE 3
#define SMEM_BYTES (NSTAGE*STAGE_BYTES) // 98304 -> 2 CTAs/SM

// wide scores smem: Ah/Al 128 rows + Bh/Bl 256 rows, 64B rows
#define W_STAGE 49152                  // 8K+8K+16K+16K
#define W_NSTAGE 3
#define W_SMEM (W_NSTAGE*W_STAGE)      // 147456 -> 1 CTA/SM

// ---------------- device scratch ----------------
__device__ __align__(256) float  g_v   [CB*CT*CD];
__device__ __align__(256) __half g_vh  [CB*CT*CD];
__device__ __align__(256) __half g_vl  [CB*CT*CD];
__device__ __align__(256) __half g_vTh [CB*CD*CT];
__device__ __align__(256) __half g_vTl [CB*CD*CT];
__device__ __align__(256) float  g_x   [(size_t)CB*CH*CT*CNH];
__device__ __align__(256) __half g_qh  [(size_t)CB*CH*CT*CNH];
__device__ __align__(256) __half g_ql  [(size_t)CB*CH*CT*CNH];
__device__ __align__(256) __half g_sh  [(size_t)CB*CH*CT*CT];   // zero-init; upper-tri stays 0
__device__ __align__(256) __half g_sl  [(size_t)CB*CH*CT*CT];
__device__ __align__(256) float  g_a   [CB*CH*CT*CD];
__device__ __align__(256) __half g_lah [CB*CH*CT*CD];
__device__ __align__(256) __half g_lal [CB*CH*CT*CD];
__device__ __align__(256) __half g_yh  [(size_t)CB*CT*CN];
__device__ __align__(256) __half g_yl  [(size_t)CB*CT*CN];
__device__ __align__(256) float  g_zp  [(size_t)8*CB*CT*CD];
__device__ __align__(256) float2 g_rope[(size_t)CT*FH];
// weights stored TRANSPOSED (K-major for B operand)
__device__ __align__(256) __half g_wxh [(size_t)CH*CD*CNH];
__device__ __align__(256) __half g_wxl [(size_t)CH*CD*CNH];
__device__ __align__(256) __half g_wyh [(size_t)CH*CD*CNH];
__device__ __align__(256) __half g_wyl [(size_t)CH*CD*CNH];
__device__ __align__(256) __half g_ench[(size_t)CN*CD];
__device__ __align__(256) __half g_encl[(size_t)CN*CD];
__device__ __align__(256) __half g_roh [CD*CV];
__device__ __align__(256) __half g_rol [CD*CV];

// ---------------- PTX helpers ----------------
__device__ __forceinline__ uint32_t smem_u32(const void* p){
    uint32_t a;
    asm("{ .reg .u64 t; cvta.to.shared.u64 t, %1; cvt.u32.u64 %0, t; }" : "=r"(a) : "l"(p));
    return a;
}
__device__ __forceinline__ void cpa16(uint32_t s, const void* g){
    asm volatile("cp.async.cg.shared.global [%0], [%1], 16;" :: "r"(s), "l"(g));
}
__device__ __forceinline__ void ldm4(uint32_t* r, uint32_t a){
    asm volatile("ldmatrix.sync.aligned.m8n8.x4.shared.b16 {%0,%1,%2,%3}, [%4];"
        : "=r"(r[0]), "=r"(r[1]), "=r"(r[2]), "=r"(r[3]) : "r"(a));
}
__device__ __forceinline__ void mma16816(float* d, const uint32_t* a, const uint32_t* b){
    asm volatile(
        "mma.sync.aligned.m16n8k16.row.col.f32.f16.f16.f32 "
        "{%0,%1,%2,%3}, {%4,%5,%6,%7}, {%8,%9}, {%0,%1,%2,%3};"
        : "+f"(d[0]), "+f"(d[1]), "+f"(d[2]), "+f"(d[3])
        : "r"(a[0]), "r"(a[1]), "r"(a[2]), "r"(a[3]), "r"(b[0]), "r"(b[1]));
}
// XOR-swizzled smem address: 64B rows, 4 x 16B chunks, chunk ^= (row>>1)&3
__device__ __forceinline__ uint32_t swadr(uint32_t row, uint32_t chunk){
    return (row << 6) + (((chunk ^ ((row >> 1) & 3u)) & 3u) << 4);
}

// ---------------- small helpers ----------------
__device__ __forceinline__ float wsum(float v){
#pragma unroll
    for (int o = 16; o > 0; o >>= 1) v += __shfl_xor_sync(0xffffffffu, v, o);
    return v;
}
__device__ __forceinline__ void split_store(__half* hi, __half* lo, size_t o, float v){
    __half h = __float2half(v);
    hi[o] = h;
    lo[o] = __float2half(v - __half2float(h));
}
__device__ __forceinline__ void split_pack(float v0, float v1, uint32_t& hi, uint32_t& lo){
    __half h0 = __float2half(v0), h1 = __float2half(v1);
    hi = (uint32_t)__half_as_ushort(h0) | ((uint32_t)__half_as_ushort(h1) << 16);
    __half l0 = __float2half(v0 - __half2float(h0));
    __half l1 = __float2half(v1 - __half2float(h1));
    lo = (uint32_t)__half_as_ushort(l0) | ((uint32_t)__half_as_ushort(l1) << 16);
}
// warp-per-row LN over 8 values/lane (256 cols)
__device__ __forceinline__ void warp_ln(float* v){
    float s = 0.f;
#pragma unroll
    for (int i = 0; i < 8; i++) s += v[i];
    float m = wsum(s) * (1.f/CD);
    float q = 0.f;
#pragma unroll
    for (int i = 0; i < 8; i++){ v[i] -= m; q += v[i]*v[i]; }
    float r = rsqrtf(wsum(q) * (1.f/CD) + EPSV);
#pragma unroll
    for (int i = 0; i < 8; i++) v[i] *= r;
}

// ---------------- merged prep kernel (tables + splitW + splitE) ----------------
#define PREP_TAB  4096
#define PREP_W    (PREP_TAB + 16384)
#define PREP_TOT  (PREP_W + 8256)

__global__ void k_prep(const float* __restrict__ dx, const float* __restrict__ dy,
                       const float* __restrict__ enc, const float* __restrict__ ro){
    int bid = blockIdx.x;
    int tid = threadIdx.x;
    if (bid < PREP_TAB){
        int i = bid;
        double ex  = (2.0 * (double)i) / (double)CNH;
        double inv = exp(-ex * 9.210340371976184);
        for (int t = tid; t < CT; t += 256){
            double ang = (double)t * inv;
            double k = rint(ang * 0.15915494309189535);
            float red = (float)(ang - k * 6.283185307179586);
            float s, c;
            sincosf(red, &s, &c);
            g_rope[(size_t)t*FH + i] = make_float2(c, s);
        }
        return;
    }
    __shared__ float tile[32][33];
    int tx = tid & 31, ty = tid >> 5;
    const float* s;
    __half *hi, *lo;
    int R, C, c0, r0;
    if (bid < PREP_W){
        int w = bid - PREP_TAB;
        int z = w >> 11;
        int rem = w & 2047;
        int cx = rem & 255;
        int cy = rem >> 8;
        if (z < 4){ s = dx + (size_t)z*CD*CNH;     hi = g_wxh + (size_t)z*CD*CNH;     lo = g_wxl + (size_t)z*CD*CNH; }
        else      { s = dy + (size_t)(z-4)*CD*CNH; hi = g_wyh + (size_t)(z-4)*CD*CNH; lo = g_wyl + (size_t)(z-4)*CD*CNH; }
        R = CD; C = CNH; c0 = cx*32; r0 = cy*32;
    } else {
        int e = bid - PREP_W;            // 0..8255
        int cx = e & 7;
        int gy = e >> 3;                 // 0..1031
        if (gy < CN/32){ s = enc; hi = g_ench; lo = g_encl; R = CN; C = CD; }
        else           { s = ro;  hi = g_roh;  lo = g_rol;  R = CD; C = CV; gy -= CN/32; }
        c0 = cx*32; r0 = gy*32;
    }
    for (int i = ty; i < 32; i += 8)
        tile[i][tx] = s[(size_t)(r0+i)*C + c0 + tx];
    __syncthreads();
    for (int i = ty; i < 32; i += 8){
        float v = tile[tx][i];
        __half hh = __float2half(v);
        size_t o = (size_t)(c0+i)*R + r0 + tx;
        hi[o] = hh;
        lo[o] = __float2half(v - __half2float(hh));
    }
}

// warp-per-row: v = ln(wte[idx])
__global__ void k_init_v(const int* __restrict__ idx, const float* __restrict__ wte){
    int gw = (blockIdx.x*256 + threadIdx.x) >> 5;
    int lane = threadIdx.x & 31;
    int b = gw >> 10, t = gw & 1023;
    const float4* src = (const float4*)(wte + (size_t)idx[gw]*CD);
    float4 x0 = src[lane], x1 = src[lane + 32];
    float v[8] = {x0.x, x0.y, x0.z, x0.w, x1.x, x1.y, x1.z, x1.w};
    warp_ln(v);
    size_t rowoff = (size_t)gw*CD;
    ((float4*)(g_v + rowoff))[lane]      = make_float4(v[0], v[1], v[2], v[3]);
    ((float4*)(g_v + rowoff))[lane + 32] = make_float4(v[4], v[5], v[6], v[7]);
#pragma unroll
    for (int half4 = 0; half4 < 2; half4++){
        int d0 = half4*128 + lane*4;
#pragma unroll
        for (int j = 0; j < 4; j += 2){
            uint32_t hi, lo;
            split_pack(v[half4*4 + j], v[half4*4 + j + 1], hi, lo);
            *(uint32_t*)(g_vh + rowoff + d0 + j) = hi;
            *(uint32_t*)(g_vl + rowoff + d0 + j) = lo;
        }
#pragma unroll
        for (int j = 0; j < 4; j++){
            int d = d0 + j;
            split_store(g_vTh, g_vTl, ((size_t)b*CD + d)*CT + t, v[half4*4 + j]);
        }
    }
}

// warp-per-row: ln(a) -> lah/lal
__global__ void k_lna(){
    int gw = (blockIdx.x*256 + threadIdx.x) >> 5;
    int lane = threadIdx.x & 31;
    size_t rowoff = (size_t)gw*CD;
    const float4* src = (const float4*)(g_a + rowoff);
    float4 x0 = src[lane], x1 = src[lane + 32];
    float v[8] = {x0.x, x0.y, x0.z, x0.w, x1.x, x1.y, x1.z, x1.w};
    warp_ln(v);
#pragma unroll
    for (int half4 = 0; half4 < 2; half4++){
        int d0 = half4*128 + lane*4;
#pragma unroll
        for (int j = 0; j < 4; j += 2){
            uint32_t hi, lo;
            split_pack(v[half4*4 + j], v[half4*4 + j + 1], hi, lo);
            *(uint32_t*)(g_lah + rowoff + d0 + j) = hi;
            *(uint32_t*)(g_lal + rowoff + d0 + j) = lo;
        }
    }
}

// warp-per-row: z = sum partials; v = ln(v + ln(z))
__global__ void k_post(){
    int gw = (blockIdx.x*256 + threadIdx.x) >> 5;
    int lane = threadIdx.x & 31;
    int b = gw >> 10, t = gw & 1023;
    size_t rowoff = (size_t)gw*CD;
    float z[8] = {0,0,0,0,0,0,0,0};
#pragma unroll
    for (int p = 0; p < 8; p++){
        const float4* zp = (const float4*)(g_zp + (size_t)p*CB*CT*CD + rowoff);
        float4 a0 = zp[lane], a1 = zp[lane + 32];
        z[0] += a0.x; z[1] += a0.y; z[2] += a0.z; z[3] += a0.w;
        z[4] += a1.x; z[5] += a1.y; z[6] += a1.z; z[7] += a1.w;
    }
    warp_ln(z);
    const float4* vs = (const float4*)(g_v + rowoff);
    float4 v0 = vs[lane], v1 = vs[lane + 32];
    float u[8] = {v0.x + z[0], v0.y + z[1], v0.z + z[2], v0.w + z[3],
                  v1.x + z[4], v1.y + z[5], v1.z + z[6], v1.w + z[7]};
    warp_ln(u);
    ((float4*)(g_v + rowoff))[lane]      = make_float4(u[0], u[1], u[2], u[3]);
    ((float4*)(g_v + rowoff))[lane + 32] = make_float4(u[4], u[5], u[6], u[7]);
#pragma unroll
    for (int half4 = 0; half4 < 2; half4++){
        int d0 = half4*128 + lane*4;
#pragma unroll
        for (int j = 0; j < 4; j += 2){
            uint32_t hi, lo;
            split_pack(u[half4*4 + j], u[half4*4 + j + 1], hi, lo);
            *(uint32_t*)(g_vh + rowoff + d0 + j) = hi;
            *(uint32_t*)(g_vl + rowoff + d0 + j) = lo;
        }
#pragma unroll
        for (int j = 0; j < 4; j++){
            int d = d0 + j;
            split_store(g_vTh, g_vTl, ((size_t)b*CD + d)*CT + t, u[half4*4 + j]);
        }
    }
}

// ---------------- wide scores kernel: 128x256 tile, 1 CTA/SM, 64x64 warp tiles ----------------
__global__ void __launch_bounds__(256) k_scores(){
    extern __shared__ __align__(128) char dyn[];
    uint32_t smb = smem_u32(dyn);

    int tid  = threadIdx.x;
    int warp = tid >> 5, lane = tid & 31;
    int wr = warp >> 2, wcc = warp & 3;         // warp tile: rows wr*64, cols wcc*64

    int bh = blockIdx.z;
    // causal tile decode: tiles per tT = tT/2 + 1 (20 total)
    int p = blockIdx.x, tT = 0, acc0 = 0;
    while (acc0 + (tT/2 + 1) <= p){ acc0 += tT/2 + 1; tT++; }
    int sT = p - acc0;
    int m0 = tT*128, n0 = sT*256;

    const __half* Ah = g_qh + (size_t)bh*CT*CNH;
    const __half* Al = g_ql + (size_t)bh*CT*CNH;

    // warp fully above/on-diag region check: skip iff s0 > t0 (64-aligned)
    bool skipWarp = (n0 + wcc*64) > (m0 + wr*64);

    float acc[4][8][4];
#pragma unroll
    for (int i = 0; i < 4; i++)
#pragma unroll
        for (int j = 0; j < 8; j++)
#pragma unroll
            for (int q = 0; q < 4; q++) acc[i][j][q] = 0.f;

    const int nch = CNH >> 5;   // 256 chunks of KC=32

    auto issue = [&](int c){
        uint32_t sbase = smb + (uint32_t)(c % W_NSTAGE) * W_STAGE;
        int kb = c << 5;
        uint32_t kc = tid & 3;
        int rlo = tid >> 2;            // 0..63
#pragma unroll
        for (int half = 0; half < 2; half++){
            uint32_t r = (uint32_t)(rlo + half*64);
            const __half* ga = Ah + (size_t)(m0 + (int)r)*CNH + kb + kc*8;
            const __half* gl = Al + (size_t)(m0 + (int)r)*CNH + kb + kc*8;
            cpa16(sbase +      swadr(r, kc), ga);
            cpa16(sbase + 8192 + swadr(r, kc), gl);
        }
#pragma unroll
        for (int q = 0; q < 4; q++){
            uint32_t r = (uint32_t)(rlo + q*64);
            const __half* gb = Ah + (size_t)(n0 + (int)r)*CNH + kb + kc*8;
            const __half* gbl = Al + (size_t)(n0 + (int)r)*CNH + kb + kc*8;
            cpa16(sbase + 16384 + swadr(r, kc), gb);
            cpa16(sbase + 32768 + swadr(r, kc), gbl);
        }
        asm volatile("cp.async.commit_group;" ::: "memory");
    };

    issue(0);
    issue(1);
    for (int c = 0; c < nch; c++){
        if (c + 1 < nch) asm volatile("cp.async.wait_group 1;" ::: "memory");
        else             asm volatile("cp.async.wait_group 0;" ::: "memory");
        __syncthreads();
        if (c + 2 < nch) issue(c + 2);

        if (skipWarp) continue;

        uint32_t sbase = smb + (uint32_t)(c % W_NSTAGE) * W_STAGE;
        uint32_t sAh = sbase, sAl = sbase + 8192;
        uint32_t sBh = sbase + 16384, sBl = sbase + 32768;

#pragma unroll
        for (int k16 = 0; k16 < 2; k16++){
            uint32_t aH[4][4], aL[4][4];
#pragma unroll
            for (int mi = 0; mi < 4; mi++){
                uint32_t row = (uint32_t)(wr*64 + mi*16 + (lane & 15));
                uint32_t ck  = (uint32_t)(k16*2 + (lane >> 4));
                uint32_t ro  = swadr(row, ck);
                ldm4(aH[mi], sAh + ro);
                ldm4(aL[mi], sAl + ro);
            }
#pragma unroll
            for (int nj2 = 0; nj2 < 4; nj2++){
                uint32_t row = (uint32_t)(wcc*64 + nj2*16 + (lane & 7) + ((lane >> 4) & 1)*8);
                uint32_t ck  = (uint32_t)(k16*2 + ((lane >> 3) & 1));
                uint32_t ro  = swadr(row, ck);
                uint32_t bh4[4], bl4[4];
                ldm4(bh4, sBh + ro);
                ldm4(bl4, sBl + ro);
#pragma unroll
                for (int mi = 0; mi < 4; mi++){
                    mma16816(acc[mi][nj2*2],     aH[mi], bh4);
                    mma16816(acc[mi][nj2*2],     aH[mi], bl4);
                    mma16816(acc[mi][nj2*2],     aL[mi], bh4);
                    mma16816(acc[mi][nj2*2 + 1], aH[mi], bh4 + 2);
                    mma16816(acc[mi][nj2*2 + 1], aH[mi], bl4 + 2);
                    mma16816(acc[mi][nj2*2 + 1], aL[mi], bh4 + 2);
                }
            }
        }
    }

    if (skipWarp) return;

    // epilogue: causal mask + split store (upper region left at its persistent 0)
#pragma unroll
    for (int mi = 0; mi < 4; mi++){
#pragma unroll
        for (int nj = 0; nj < 8; nj++){
            int rb = wr*64 + mi*16 + (lane >> 2);
            int cb = wcc*64 + nj*8 + ((lane & 3) << 1);
#pragma unroll
            for (int hrow = 0; hrow < 2; hrow++){
                int r = rb + hrow*8;
                int t = m0 + r;
                int s = n0 + cb;
                if (s >= t) continue;
                float v0 = acc[mi][nj][hrow*2];
                float v1 = acc[mi][nj][hrow*2 + 1];
                if (s + 1 >= t) v1 = 0.f;
                uint32_t hi, lo;
                split_pack(v0, v1, hi, lo);
                size_t o = (size_t)bh*CT*CT + (size_t)t*CT + s;
                *(uint32_t*)(g_sh + o) = hi;
                *(uint32_t*)(g_sl + o) = lo;
            }
        }
    }
}

// ---------------- unified split-fp16 mma.sync GEMM (narrow modes) ----------------
#define M_XPROJ  0
#define M_AMODE  2
#define M_YPROJ  3
#define M_ENC    4
#define M_RO     5

template<int MODE>
__global__ void __launch_bounds__(256, 2) k_gemm(float* out_arg){
    extern __shared__ __align__(128) char dyn[];
    uint32_t smb = smem_u32(dyn);

    // static weight operand B: drop the Ah*Bl residual term (2-term split)
    constexpr bool DROPBL = (MODE == M_XPROJ || MODE == M_YPROJ ||
                             MODE == M_ENC   || MODE == M_RO);

    int tid  = threadIdx.x;
    int warp = tid >> 5, lane = tid & 31;
    int wr = warp >> 1, wc = warp & 1;          // warp tile: rows wr*32, cols wc*64

    int bh = blockIdx.z, b = bh >> 2, h = bh & 3;
    const __half *Ah, *Al, *Bh, *Bl;
    size_t lda, ldb;
    int m0, n0, Klen;

    if (MODE == M_XPROJ){
        Ah = g_vh + (size_t)b*CT*CD;   Al = g_vl + (size_t)b*CT*CD;   lda = CD;
        Bh = g_wxh + (size_t)h*CD*CNH; Bl = g_wxl + (size_t)h*CD*CNH; ldb = CD;
        m0 = blockIdx.y*128; n0 = blockIdx.x*128; Klen = CD;
    } else if (MODE == M_YPROJ){
        Ah = g_lah + (size_t)bh*CT*CD; Al = g_lal + (size_t)bh*CT*CD; lda = CD;
        Bh = g_wyh + (size_t)h*CD*CNH; Bl = g_wyl + (size_t)h*CD*CNH; ldb = CD;
        m0 = blockIdx.y*128; n0 = blockIdx.x*128; Klen = CD;
    } else if (MODE == M_AMODE){
        Ah = g_sh + (size_t)bh*CT*CT;  Al = g_sl + (size_t)bh*CT*CT;  lda = CT;
        Bh = g_vTh + (size_t)b*CD*CT;  Bl = g_vTl + (size_t)b*CD*CT;  ldb = CT;
        m0 = blockIdx.y*128; n0 = blockIdx.x*128;
        Klen = (blockIdx.y + 1) * 128;                // causal K clamp
    } else if (MODE == M_ENC){
        int z = blockIdx.z;
        Ah = g_yh + (size_t)z*4096;   Al = g_yl + (size_t)z*4096;   lda = CN;
        Bh = g_ench + (size_t)z*4096; Bl = g_encl + (size_t)z*4096; ldb = CN;
        m0 = blockIdx.y*128; n0 = blockIdx.x*128; Klen = 4096;
    } else { // M_RO
        Ah = g_vh; Al = g_vl; lda = CD;
        Bh = g_roh; Bl = g_rol; ldb = CD;
        m0 = blockIdx.y*128; n0 = blockIdx.x*128; Klen = CD;
    }

    float acc[2][8][4];
#pragma unroll
    for (int i = 0; i < 2; i++)
#pragma unroll
        for (int j = 0; j < 8; j++)
#pragma unroll
            for (int q = 0; q < 4; q++) acc[i][j][q] = 0.f;

    const int nch = Klen >> 5;   // KC = 32 halves per chunk

    auto issue = [&](int c){
        uint32_t sbase = smb + (uint32_t)(c % NSTAGE) * STAGE_BYTES;
        int kb = c << 5;
        uint32_t kc = tid & 3;
        int rlo = tid >> 2;
        int nArr = DROPBL ? 3 : 4;
#pragma unroll
        for (int it = 0; it < 8; it++){
            int arr = it >> 1;
            if (arr >= nArr) break;
            uint32_t r = (uint32_t)(((it & 1) << 6) + rlo);
            const __half* gp = (arr == 0) ? Ah : (arr == 1) ? Al : (arr == 2) ? Bh : Bl;
            size_t ld  = (arr < 2) ? lda : ldb;
            int    off = (arr < 2) ? m0  : n0;
            cpa16(sbase + (uint32_t)arr*ARR_BYTES + swadr(r, kc),
                  gp + ((size_t)(off + (int)r))*ld + kb + kc*8);
        }
        asm volatile("cp.async.commit_group;" ::: "memory");
    };

    issue(0);
    issue(1);
    for (int c = 0; c < nch; c++){
        if (c + 1 < nch) asm volatile("cp.async.wait_group 1;" ::: "memory");
        else             asm volatile("cp.async.wait_group 0;" ::: "memory");
        __syncthreads();
        if (c + 2 < nch) issue(c + 2);

        uint32_t sbase = smb + (uint32_t)(c % NSTAGE) * STAGE_BYTES;
        uint32_t sAh = sbase, sAl = sbase + ARR_BYTES;
        uint32_t sBh = sbase + 2*ARR_BYTES, sBl = sbase + 3*ARR_BYTES;

#pragma unroll
        for (int k16 = 0; k16 < 2; k16++){
            uint32_t aH[2][4], aL[2][4];
#pragma unroll
            for (int mi = 0; mi < 2; mi++){
                uint32_t row = (uint32_t)(wr*32 + mi*16 + (lane & 15));
                uint32_t ck  = (uint32_t)(k16*2 + (lane >> 4));
                uint32_t ro  = swadr(row, ck);
                ldm4(aH[mi], sAh + ro);
                ldm4(aL[mi], sAl + ro);
            }
#pragma unroll
            for (int nj2 = 0; nj2 < 4; nj2++){
                uint32_t row = (uint32_t)(wc*64 + nj2*16 + (lane & 7) + ((lane >> 4) & 1)*8);
                uint32_t ck  = (uint32_t)(k16*2 + ((lane >> 3) & 1));
                uint32_t ro  = swadr(row, ck);
                uint32_t bh4[4];
                ldm4(bh4, sBh + ro);
                if (DROPBL){
#pragma unroll
                    for (int mi = 0; mi < 2; mi++){
                        mma16816(acc[mi][nj2*2],     aH[mi], bh4);
                        mma16816(acc[mi][nj2*2],     aL[mi], bh4);
                        mma16816(acc[mi][nj2*2 + 1], aH[mi], bh4 + 2);
                        mma16816(acc[mi][nj2*2 + 1], aL[mi], bh4 + 2);
                    }
                } else {
                    uint32_t bl4[4];
                    ldm4(bl4, sBl + ro);
#pragma unroll
                    for (int mi = 0; mi < 2; mi++){
                        mma16816(acc[mi][nj2*2],     aH[mi], bh4);
                        mma16816(acc[mi][nj2*2],     aH[mi], bl4);
                        mma16816(acc[mi][nj2*2],     aL[mi], bh4);
                        mma16816(acc[mi][nj2*2 + 1], aH[mi], bh4 + 2);
                        mma16816(acc[mi][nj2*2 + 1], aH[mi], bl4 + 2);
                        mma16816(acc[mi][nj2*2 + 1], aL[mi], bh4 + 2);
                    }
                }
            }
        }
    }

    // ---------------- epilogue ----------------
#pragma unroll
    for (int mi = 0; mi < 2; mi++){
#pragma unroll
        for (int nj = 0; nj < 8; nj++){
            int rb = wr*32 + mi*16 + (lane >> 2);
            int cb = wc*64 + nj*8 + ((lane & 3) << 1);
#pragma unroll
            for (int hrow = 0; hrow < 2; hrow++){
                int r = rb + hrow*8;
                float v0 = acc[mi][nj][hrow*2];
                float v1 = acc[mi][nj][hrow*2 + 1];
                int t = m0 + r;

                if (MODE == M_XPROJ){
                    int n = n0 + cb;
                    float x1 = fmaxf(v0, 0.f), x2 = fmaxf(v1, 0.f);
                    size_t xi = (size_t)bh*CT*CNH + (size_t)t*CNH + n;
                    *(float2*)(g_x + xi) = make_float2(x1, x2);
                    float2 cs2 = g_rope[(size_t)t*FH + (n >> 1)];
                    float q1 = x1*cs2.x - x2*cs2.y;
                    float q2 = x1*cs2.y + x2*cs2.x;
                    uint32_t hi, lo;
                    split_pack(q1, q2, hi, lo);
                    *(uint32_t*)(g_qh + xi) = hi;
                    *(uint32_t*)(g_ql + xi) = lo;
                } else if (MODE == M_YPROJ){
                    int n = n0 + cb;
                    size_t xi = (size_t)bh*CT*CNH + (size_t)t*CNH + n;
                    float2 xv = *(const float2*)(g_x + xi);
                    float y1 = fmaxf(v0, 0.f) * xv.x;
                    float y2 = fmaxf(v1, 0.f) * xv.y;
                    uint32_t hi, lo;
                    split_pack(y1, y2, hi, lo);
                    size_t yi = ((size_t)b*CT + t)*CN + (size_t)h*CNH + n;
                    *(uint32_t*)(g_yh + yi) = hi;
                    *(uint32_t*)(g_yl + yi) = lo;
                } else {
                    float* op; size_t ldo;
                    if (MODE == M_AMODE){ op = g_a + (size_t)bh*CT*CD; ldo = CD; }
                    else if (MODE == M_ENC){ op = g_zp + (size_t)blockIdx.z*CB*CT*CD; ldo = CD; }
                    else { op = out_arg; ldo = CV; }
                    *(float2*)(op + (size_t)t*ldo + n0 + cb) = make_float2(v0, v1);
                }
            }
        }
    }
}

// ---------------- launch ----------------
extern "C" void kernel_launch(void* const* d_in, const int* in_sizes, int n_in,
                              void* d_out, int out_size){
    const int*   idx = (const int*)  d_in[0];
    const float* wte = (const float*)d_in[1];
    const float* enc = (const float*)d_in[2];
    const float* dx  = (const float*)d_in[3];
    const float* dy  = (const float*)d_in[4];
    const float* ro  = (const float*)d_in[5];
    float* out = (float*)d_out;

    cudaFuncSetAttribute(k_gemm<M_XPROJ>,  cudaFuncAttributeMaxDynamicSharedMemorySize, SMEM_BYTES);
    cudaFuncSetAttribute(k_scores,         cudaFuncAttributeMaxDynamicSharedMemorySize, W_SMEM);
    cudaFuncSetAttribute(k_gemm<M_AMODE>,  cudaFuncAttributeMaxDynamicSharedMemorySize, SMEM_BYTES);
    cudaFuncSetAttribute(k_gemm<M_YPROJ>,  cudaFuncAttributeMaxDynamicSharedMemorySize, SMEM_BYTES);
    cudaFuncSetAttribute(k_gemm<M_ENC>,    cudaFuncAttributeMaxDynamicSharedMemorySize, SMEM_BYTES);
    cudaFuncSetAttribute(k_gemm<M_RO>,     cudaFuncAttributeMaxDynamicSharedMemorySize, SMEM_BYTES);

    // launch order: 0 k_prep, 1 k_init_v, 2 xproj, 3 SCORES (ncu capture slot), ...
    k_prep<<<PREP_TOT, 256>>>(dx, dy, enc, ro);
    k_init_v<<<CB*CT/8, 256>>>(idx, wte);

    for (int l = 0; l < CL; l++){
        k_gemm<M_XPROJ> <<<dim3(CNH/128, CT/128, CB*CH), 256, SMEM_BYTES>>>(nullptr);
        k_scores        <<<dim3(20,      1,      CB*CH), 256, W_SMEM>>>();
        k_gemm<M_AMODE> <<<dim3(CD/128,  CT/128, CB*CH), 256, SMEM_BYTES>>>(nullptr);
        k_lna<<<CB*CH*CT/8, 256>>>();
        k_gemm<M_YPROJ> <<<dim3(CNH/128, CT/128, CB*CH), 256, SMEM_BYTES>>>(nullptr);
        k_gemm<M_ENC>   <<<dim3(CD/128, (CB*CT)/128, 8), 256, SMEM_BYTES>>>(nullptr);
        k_post<<<CB*CT/8, 256>>>();
    }
    k_gemm<M_RO><<<dim3(CV/128, (CB*CT)/128, 1), 256, SMEM_BYTES>>>(out);
}

// round 14
// speedup vs baseline: 1.4200x; 1.4200x over previous
#include <cuda_runtime.h>
#include <cuda_fp16.h>
#include <math.h>
#include <stdint.h>

#define CB 2
#define CT 1024
#define CD 256
#define CH 4
#define CNH 8192
#define CN 32768
#define CV 256
#define CL 6
#define FH 4096
#define EPSV 1e-5f

// smem geometry: 4 arrays (Ah, Al, Bh, Bl), 128 rows x 64B (KC=32), XOR-swizzled
#define ARR_BYTES (128*64)             // 8192
#define STAGE_BYTES (4*ARR_BYTES)      // 32768
#define NSTAGE 3
#define SMEM_BYTES (NSTAGE*STAGE_BYTES) // 98304 -> 2 CTAs/SM

// ---------------- device scratch ----------------
__device__ __align__(256) float  g_v   [CB*CT*CD];
__device__ __align__(256) __half g_vh  [CB*CT*CD];
__device__ __align__(256) __half g_vl  [CB*CT*CD];
__device__ __align__(256) __half g_vTh [CB*CD*CT];
__device__ __align__(256) __half g_vTl [CB*CD*CT];
__device__ __align__(256) float  g_x   [(size_t)CB*CH*CT*CNH];
__device__ __align__(256) __half g_qh  [(size_t)CB*CH*CT*CNH];
__device__ __align__(256) __half g_ql  [(size_t)CB*CH*CT*CNH];
__device__ __align__(256) __half g_sh  [(size_t)CB*CH*CT*CT];   // zero-init; upper-tri stays 0
__device__ __align__(256) __half g_sl  [(size_t)CB*CH*CT*CT];
__device__ __align__(256) float  g_a   [CB*CH*CT*CD];
__device__ __align__(256) __half g_lah [CB*CH*CT*CD];
__device__ __align__(256) __half g_lal [CB*CH*CT*CD];
__device__ __align__(256) __half g_yh  [(size_t)CB*CT*CN];
__device__ __align__(256) __half g_yl  [(size_t)CB*CT*CN];
__device__ __align__(256) float  g_zp  [(size_t)8*CB*CT*CD];
__device__ __align__(256) float2 g_rope[(size_t)CT*FH];
// weights stored TRANSPOSED (K-major for B operand)
__device__ __align__(256) __half g_wxh [(size_t)CH*CD*CNH];
__device__ __align__(256) __half g_wxl [(size_t)CH*CD*CNH];
__device__ __align__(256) __half g_wyh [(size_t)CH*CD*CNH];
__device__ __align__(256) __half g_wyl [(size_t)CH*CD*CNH];
__device__ __align__(256) __half g_ench[(size_t)CN*CD];
__device__ __align__(256) __half g_encl[(size_t)CN*CD];
__device__ __align__(256) __half g_roh [CD*CV];
__device__ __align__(256) __half g_rol [CD*CV];

// ---------------- PTX helpers ----------------
__device__ __forceinline__ uint32_t smem_u32(const void* p){
    uint32_t a;
    asm("{ .reg .u64 t; cvta.to.shared.u64 t, %1; cvt.u32.u64 %0, t; }" : "=r"(a) : "l"(p));
    return a;
}
__device__ __forceinline__ void cpa16(uint32_t s, const void* g){
    asm volatile("cp.async.cg.shared.global [%0], [%1], 16;" :: "r"(s), "l"(g));
}
__device__ __forceinline__ void ldm4(uint32_t* r, uint32_t a){
    asm volatile("ldmatrix.sync.aligned.m8n8.x4.shared.b16 {%0,%1,%2,%3}, [%4];"
        : "=r"(r[0]), "=r"(r[1]), "=r"(r[2]), "=r"(r[3]) : "r"(a));
}
__device__ __forceinline__ void mma16816(float* d, const uint32_t* a, const uint32_t* b){
    asm volatile(
        "mma.sync.aligned.m16n8k16.row.col.f32.f16.f16.f32 "
        "{%0,%1,%2,%3}, {%4,%5,%6,%7}, {%8,%9}, {%0,%1,%2,%3};"
        : "+f"(d[0]), "+f"(d[1]), "+f"(d[2]), "+f"(d[3])
        : "r"(a[0]), "r"(a[1]), "r"(a[2]), "r"(a[3]), "r"(b[0]), "r"(b[1]));
}
// XOR-swizzled smem address: 64B rows, 4 x 16B chunks, chunk ^= (row>>1)&3
__device__ __forceinline__ uint32_t swadr(uint32_t row, uint32_t chunk){
    return (row << 6) + (((chunk ^ ((row >> 1) & 3u)) & 3u) << 4);
}

// ---------------- small helpers ----------------
__device__ __forceinline__ float wsum(float v){
#pragma unroll
    for (int o = 16; o > 0; o >>= 1) v += __shfl_xor_sync(0xffffffffu, v, o);
    return v;
}
__device__ __forceinline__ void split_store(__half* hi, __half* lo, size_t o, float v){
    __half h = __float2half(v);
    hi[o] = h;
    lo[o] = __float2half(v - __half2float(h));
}
__device__ __forceinline__ void split_pack(float v0, float v1, uint32_t& hi, uint32_t& lo){
    __half h0 = __float2half(v0), h1 = __float2half(v1);
    hi = (uint32_t)__half_as_ushort(h0) | ((uint32_t)__half_as_ushort(h1) << 16);
    __half l0 = __float2half(v0 - __half2float(h0));
    __half l1 = __float2half(v1 - __half2float(h1));
    lo = (uint32_t)__half_as_ushort(l0) | ((uint32_t)__half_as_ushort(l1) << 16);
}
// warp-per-row LN over 8 values/lane (256 cols)
__device__ __forceinline__ void warp_ln(float* v){
    float s = 0.f;
#pragma unroll
    for (int i = 0; i < 8; i++) s += v[i];
    float m = wsum(s) * (1.f/CD);
    float q = 0.f;
#pragma unroll
    for (int i = 0; i < 8; i++){ v[i] -= m; q += v[i]*v[i]; }
    float r = rsqrtf(wsum(q) * (1.f/CD) + EPSV);
#pragma unroll
    for (int i = 0; i < 8; i++) v[i] *= r;
}

// ---------------- merged prep kernel (tables + splitW + splitE) ----------------
// grid layout (1-D): [0,4096) tables | [4096,20480) splitW | [20480,28736) splitE
#define PREP_TAB  4096
#define PREP_W    (PREP_TAB + 16384)
#define PREP_TOT  (PREP_W + 8256)

__global__ void k_prep(const float* __restrict__ dx, const float* __restrict__ dy,
                       const float* __restrict__ enc, const float* __restrict__ ro){
    int bid = blockIdx.x;
    int tid = threadIdx.x;
    if (bid < PREP_TAB){
        int i = bid;
        double ex  = (2.0 * (double)i) / (double)CNH;
        double inv = exp(-ex * 9.210340371976184);
        for (int t = tid; t < CT; t += 256){
            double ang = (double)t * inv;
            double k = rint(ang * 0.15915494309189535);
            float red = (float)(ang - k * 6.283185307179586);
            float s, c;
            sincosf(red, &s, &c);
            g_rope[(size_t)t*FH + i] = make_float2(c, s);
        }
        return;
    }
    __shared__ float tile[32][33];
    int tx = tid & 31, ty = tid >> 5;
    const float* s;
    __half *hi, *lo;
    int R, C, c0, r0;
    if (bid < PREP_W){
        int w = bid - PREP_TAB;
        int z = w >> 11;
        int rem = w & 2047;
        int cx = rem & 255;
        int cy = rem >> 8;
        if (z < 4){ s = dx + (size_t)z*CD*CNH;     hi = g_wxh + (size_t)z*CD*CNH;     lo = g_wxl + (size_t)z*CD*CNH; }
        else      { s = dy + (size_t)(z-4)*CD*CNH; hi = g_wyh + (size_t)(z-4)*CD*CNH; lo = g_wyl + (size_t)(z-4)*CD*CNH; }
        R = CD; C = CNH; c0 = cx*32; r0 = cy*32;
    } else {
        int e = bid - PREP_W;            // 0..8255
        int cx = e & 7;
        int gy = e >> 3;                 // 0..1031
        if (gy < CN/32){ s = enc; hi = g_ench; lo = g_encl; R = CN; C = CD; }
        else           { s = ro;  hi = g_roh;  lo = g_rol;  R = CD; C = CV; gy -= CN/32; }
        c0 = cx*32; r0 = gy*32;
    }
    for (int i = ty; i < 32; i += 8)
        tile[i][tx] = s[(size_t)(r0+i)*C + c0 + tx];
    __syncthreads();
    for (int i = ty; i < 32; i += 8){
        float v = tile[tx][i];
        __half hh = __float2half(v);
        size_t o = (size_t)(c0+i)*R + r0 + tx;
        hi[o] = hh;
        lo[o] = __float2half(v - __half2float(hh));
    }
}

// warp-per-row: v = ln(wte[idx])
__global__ void k_init_v(const int* __restrict__ idx, const float* __restrict__ wte){
    int gw = (blockIdx.x*256 + threadIdx.x) >> 5;
    int lane = threadIdx.x & 31;
    int b = gw >> 10, t = gw & 1023;
    const float4* src = (const float4*)(wte + (size_t)idx[gw]*CD);
    float4 x0 = src[lane], x1 = src[lane + 32];
    float v[8] = {x0.x, x0.y, x0.z, x0.w, x1.x, x1.y, x1.z, x1.w};
    warp_ln(v);
    size_t rowoff = (size_t)gw*CD;
    ((float4*)(g_v + rowoff))[lane]      = make_float4(v[0], v[1], v[2], v[3]);
    ((float4*)(g_v + rowoff))[lane + 32] = make_float4(v[4], v[5], v[6], v[7]);
#pragma unroll
    for (int half4 = 0; half4 < 2; half4++){
        int d0 = half4*128 + lane*4;
#pragma unroll
        for (int j = 0; j < 4; j += 2){
            uint32_t hi, lo;
            split_pack(v[half4*4 + j], v[half4*4 + j + 1], hi, lo);
            *(uint32_t*)(g_vh + rowoff + d0 + j) = hi;
            *(uint32_t*)(g_vl + rowoff + d0 + j) = lo;
        }
#pragma unroll
        for (int j = 0; j < 4; j++){
            int d = d0 + j;
            split_store(g_vTh, g_vTl, ((size_t)b*CD + d)*CT + t, v[half4*4 + j]);
        }
    }
}

// warp-per-row: ln(a) -> lah/lal
__global__ void k_lna(){
    int gw = (blockIdx.x*256 + threadIdx.x) >> 5;
    int lane = threadIdx.x & 31;
    size_t rowoff = (size_t)gw*CD;
    const float4* src = (const float4*)(g_a + rowoff);
    float4 x0 = src[lane], x1 = src[lane + 32];
    float v[8] = {x0.x, x0.y, x0.z, x0.w, x1.x, x1.y, x1.z, x1.w};
    warp_ln(v);
#pragma unroll
    for (int half4 = 0; half4 < 2; half4++){
        int d0 = half4*128 + lane*4;
#pragma unroll
        for (int j = 0; j < 4; j += 2){
            uint32_t hi, lo;
            split_pack(v[half4*4 + j], v[half4*4 + j + 1], hi, lo);
            *(uint32_t*)(g_lah + rowoff + d0 + j) = hi;
            *(uint32_t*)(g_lal + rowoff + d0 + j) = lo;
        }
    }
}

// warp-per-row: z = sum partials; v = ln(v + ln(z))
__global__ void k_post(){
    int gw = (blockIdx.x*256 + threadIdx.x) >> 5;
    int lane = threadIdx.x & 31;
    int b = gw >> 10, t = gw & 1023;
    size_t rowoff = (size_t)gw*CD;
    float z[8] = {0,0,0,0,0,0,0,0};
#pragma unroll
    for (int p = 0; p < 8; p++){
        const float4* zp = (const float4*)(g_zp + (size_t)p*CB*CT*CD + rowoff);
        float4 a0 = zp[lane], a1 = zp[lane + 32];
        z[0] += a0.x; z[1] += a0.y; z[2] += a0.z; z[3] += a0.w;
        z[4] += a1.x; z[5] += a1.y; z[6] += a1.z; z[7] += a1.w;
    }
    warp_ln(z);
    const float4* vs = (const float4*)(g_v + rowoff);
    float4 v0 = vs[lane], v1 = vs[lane + 32];
    float u[8] = {v0.x + z[0], v0.y + z[1], v0.z + z[2], v0.w + z[3],
                  v1.x + z[4], v1.y + z[5], v1.z + z[6], v1.w + z[7]};
    warp_ln(u);
    ((float4*)(g_v + rowoff))[lane]      = make_float4(u[0], u[1], u[2], u[3]);
    ((float4*)(g_v + rowoff))[lane + 32] = make_float4(u[4], u[5], u[6], u[7]);
#pragma unroll
    for (int half4 = 0; half4 < 2; half4++){
        int d0 = half4*128 + lane*4;
#pragma unroll
        for (int j = 0; j < 4; j += 2){
            uint32_t hi, lo;
            split_pack(u[half4*4 + j], u[half4*4 + j + 1], hi, lo);
            *(uint32_t*)(g_vh + rowoff + d0 + j) = hi;
            *(uint32_t*)(g_vl + rowoff + d0 + j) = lo;
        }
#pragma unroll
        for (int j = 0; j < 4; j++){
            int d = d0 + j;
            split_store(g_vTh, g_vTl, ((size_t)b*CD + d)*CT + t, u[half4*4 + j]);
        }
    }
}

// ---------------- unified split-fp16 mma.sync GEMM ----------------
#define M_XPROJ  0
#define M_SCORES 1
#define M_AMODE  2
#define M_YPROJ  3
#define M_ENC    4
#define M_RO     5

template<int MODE>
__global__ void __launch_bounds__(256, 2) k_gemm(float* out_arg){
    extern __shared__ __align__(128) char dyn[];
    uint32_t smb = smem_u32(dyn);

    // static weight operand B: drop the Ah*Bl residual term (2-term split)
    constexpr bool DROPBL = (MODE == M_XPROJ || MODE == M_YPROJ ||
                             MODE == M_ENC   || MODE == M_RO);

    int tid  = threadIdx.x;
    int warp = tid >> 5, lane = tid & 31;
    int wr = warp >> 1, wc = warp & 1;          // warp tile: rows wr*32, cols wc*64

    int bh = blockIdx.z, b = bh >> 2, h = bh & 3;
    const __half *Ah, *Al, *Bh, *Bl;
    size_t lda, ldb;
    int m0, n0, Klen;
    bool shareB = false;

    if (MODE == M_XPROJ){
        Ah = g_vh + (size_t)b*CT*CD;   Al = g_vl + (size_t)b*CT*CD;   lda = CD;
        Bh = g_wxh + (size_t)h*CD*CNH; Bl = g_wxl + (size_t)h*CD*CNH; ldb = CD;
        m0 = blockIdx.y*128; n0 = blockIdx.x*128; Klen = CD;
    } else if (MODE == M_YPROJ){
        Ah = g_lah + (size_t)bh*CT*CD; Al = g_lal + (size_t)bh*CT*CD; lda = CD;
        Bh = g_wyh + (size_t)h*CD*CNH; Bl = g_wyl + (size_t)h*CD*CNH; ldb = CD;
        m0 = blockIdx.y*128; n0 = blockIdx.x*128; Klen = CD;
    } else if (MODE == M_SCORES){
        int p = blockIdx.x, tT = 0, acc0 = 0;
        while (acc0 + tT + 1 <= p){ tT++; acc0 += tT; }
        int sT = p - acc0;
        Ah = g_qh + (size_t)bh*CT*CNH; Al = g_ql + (size_t)bh*CT*CNH; lda = CNH;
        Bh = Ah; Bl = Al; ldb = CNH;
        m0 = tT*128; n0 = sT*128; Klen = CNH;
        shareB = (tT == sT);
    } else if (MODE == M_AMODE){
        Ah = g_sh + (size_t)bh*CT*CT;  Al = g_sl + (size_t)bh*CT*CT;  lda = CT;
        Bh = g_vTh + (size_t)b*CD*CT;  Bl = g_vTl + (size_t)b*CD*CT;  ldb = CT;
        m0 = blockIdx.y*128; n0 = blockIdx.x*128;
        Klen = (blockIdx.y + 1) * 128;                // causal K clamp
    } else if (MODE == M_ENC){
        int z = blockIdx.z;
        Ah = g_yh + (size_t)z*4096;   Al = g_yl + (size_t)z*4096;   lda = CN;
        Bh = g_ench + (size_t)z*4096; Bl = g_encl + (size_t)z*4096; ldb = CN;
        m0 = blockIdx.y*128; n0 = blockIdx.x*128; Klen = 4096;
    } else { // M_RO
        Ah = g_vh; Al = g_vl; lda = CD;
        Bh = g_roh; Bl = g_rol; ldb = CD;
        m0 = blockIdx.y*128; n0 = blockIdx.x*128; Klen = CD;
    }

    float acc[2][8][4];
#pragma unroll
    for (int i = 0; i < 2; i++)
#pragma unroll
        for (int j = 0; j < 8; j++)
#pragma unroll
            for (int q = 0; q < 4; q++) acc[i][j][q] = 0.f;

    const int nch = Klen >> 5;   // KC = 32 halves per chunk

    // ---- async stage issuer: up to 4 arrays x 128 rows x 4 x 16B (swizzled) ----
    auto issue = [&](int c){
        uint32_t sbase = smb + (uint32_t)(c % NSTAGE) * STAGE_BYTES;
        int kb = c << 5;
        uint32_t kc = tid & 3;         // 16B chunk in 64B row
        int rlo = tid >> 2;            // 0..63
        int nArr = shareB ? 2 : (DROPBL ? 3 : 4);
#pragma unroll
        for (int it = 0; it < 8; it++){
            int arr = it >> 1;                       // 0=Ah 1=Al 2=Bh 3=Bl
            if (arr >= nArr) break;
            uint32_t r = (uint32_t)(((it & 1) << 6) + rlo);  // 0..127
            const __half* gp = (arr == 0) ? Ah : (arr == 1) ? Al : (arr == 2) ? Bh : Bl;
            size_t ld  = (arr < 2) ? lda : ldb;
            int    off = (arr < 2) ? m0  : n0;
            cpa16(sbase + (uint32_t)arr*ARR_BYTES + swadr(r, kc),
                  gp + ((size_t)(off + (int)r))*ld + kb + kc*8);
        }
        asm volatile("cp.async.commit_group;" ::: "memory");
    };

    issue(0);
    issue(1);
    for (int c = 0; c < nch; c++){
        if (c + 1 < nch) asm volatile("cp.async.wait_group 1;" ::: "memory");
        else             asm volatile("cp.async.wait_group 0;" ::: "memory");
        __syncthreads();          // single barrier per chunk
        if (c + 2 < nch) issue(c + 2);

        uint32_t sbase = smb + (uint32_t)(c % NSTAGE) * STAGE_BYTES;
        uint32_t sAh = sbase, sAl = sbase + ARR_BYTES;
        uint32_t sBh = shareB ? sAh : (sbase + 2*ARR_BYTES);
        uint32_t sBl = shareB ? sAl : (sbase + 3*ARR_BYTES);

#pragma unroll
        for (int k16 = 0; k16 < 2; k16++){
            uint32_t aH[2][4], aL[2][4];
#pragma unroll
            for (int mi = 0; mi < 2; mi++){
                uint32_t row = (uint32_t)(wr*32 + mi*16 + (lane & 15));
                uint32_t ck  = (uint32_t)(k16*2 + (lane >> 4));
                uint32_t ro  = swadr(row, ck);
                ldm4(aH[mi], sAh + ro);
                ldm4(aL[mi], sAl + ro);
            }
#pragma unroll
            for (int nj2 = 0; nj2 < 4; nj2++){
                uint32_t row = (uint32_t)(wc*64 + nj2*16 + (lane & 7) + ((lane >> 4) & 1)*8);
                uint32_t ck  = (uint32_t)(k16*2 + ((lane >> 3) & 1));
                uint32_t ro  = swadr(row, ck);
                uint32_t bh4[4];
                ldm4(bh4, sBh + ro);
                if (DROPBL){
#pragma unroll
                    for (int mi = 0; mi < 2; mi++){
                        mma16816(acc[mi][nj2*2],     aH[mi], bh4);
                        mma16816(acc[mi][nj2*2],     aL[mi], bh4);
                        mma16816(acc[mi][nj2*2 + 1], aH[mi], bh4 + 2);
                        mma16816(acc[mi][nj2*2 + 1], aL[mi], bh4 + 2);
                    }
                } else {
                    uint32_t bl4[4];
                    ldm4(bl4, sBl + ro);
#pragma unroll
                    for (int mi = 0; mi < 2; mi++){
                        mma16816(acc[mi][nj2*2],     aH[mi], bh4);
                        mma16816(acc[mi][nj2*2],     aH[mi], bl4);
                        mma16816(acc[mi][nj2*2],     aL[mi], bh4);
                        mma16816(acc[mi][nj2*2 + 1], aH[mi], bh4 + 2);
                        mma16816(acc[mi][nj2*2 + 1], aH[mi], bl4 + 2);
                        mma16816(acc[mi][nj2*2 + 1], aL[mi], bh4 + 2);
                    }
                }
            }
        }
    }

    // ---------------- epilogue: direct from accumulators ----------------
#pragma unroll
    for (int mi = 0; mi < 2; mi++){
#pragma unroll
        for (int nj = 0; nj < 8; nj++){
            int rb = wr*32 + mi*16 + (lane >> 2);
            int cb = wc*64 + nj*8 + ((lane & 3) << 1);
#pragma unroll
            for (int hrow = 0; hrow < 2; hrow++){
                int r = rb + hrow*8;
                float v0 = acc[mi][nj][hrow*2];
                float v1 = acc[mi][nj][hrow*2 + 1];
                int t = m0 + r;

                if (MODE == M_SCORES){
                    int s = n0 + cb;
                    if (s >= t) continue;              // masked pair: region persistently 0
                    if (s + 1 >= t) v1 = 0.f;
                    uint32_t hi, lo;
                    split_pack(v0, v1, hi, lo);
                    size_t o = (size_t)bh*CT*CT + (size_t)t*CT + s;
                    *(uint32_t*)(g_sh + o) = hi;
                    *(uint32_t*)(g_sl + o) = lo;
                } else if (MODE == M_XPROJ){
                    int n = n0 + cb;
                    float x1 = fmaxf(v0, 0.f), x2 = fmaxf(v1, 0.f);
                    size_t xi = (size_t)bh*CT*CNH + (size_t)t*CNH + n;
                    *(float2*)(g_x + xi) = make_float2(x1, x2);
                    float2 cs2 = g_rope[(size_t)t*FH + (n >> 1)];
                    float q1 = x1*cs2.x - x2*cs2.y;
                    float q2 = x1*cs2.y + x2*cs2.x;
                    uint32_t hi, lo;
                    split_pack(q1, q2, hi, lo);
                    *(uint32_t*)(g_qh + xi) = hi;
                    *(uint32_t*)(g_ql + xi) = lo;
                } else if (MODE == M_YPROJ){
                    int n = n0 + cb;
                    size_t xi = (size_t)bh*CT*CNH + (size_t)t*CNH + n;
                    float2 xv = *(const float2*)(g_x + xi);
                    float y1 = fmaxf(v0, 0.f) * xv.x;
                    float y2 = fmaxf(v1, 0.f) * xv.y;
                    uint32_t hi, lo;
                    split_pack(y1, y2, hi, lo);
                    size_t yi = ((size_t)b*CT + t)*CN + (size_t)h*CNH + n;
                    *(uint32_t*)(g_yh + yi) = hi;
                    *(uint32_t*)(g_yl + yi) = lo;
                } else {
                    float* op; size_t ldo;
                    if (MODE == M_AMODE){ op = g_a + (size_t)bh*CT*CD; ldo = CD; }
                    else if (MODE == M_ENC){ op = g_zp + (size_t)blockIdx.z*CB*CT*CD; ldo = CD; }
                    else { op = out_arg; ldo = CV; }
                    *(float2*)(op + (size_t)t*ldo + n0 + cb) = make_float2(v0, v1);
                }
            }
        }
    }
}

// ---------------- launch ----------------
extern "C" void kernel_launch(void* const* d_in, const int* in_sizes, int n_in,
                              void* d_out, int out_size){
    const int*   idx = (const int*)  d_in[0];
    const float* wte = (const float*)d_in[1];
    const float* enc = (const float*)d_in[2];
    const float* dx  = (const float*)d_in[3];
    const float* dy  = (const float*)d_in[4];
    const float* ro  = (const float*)d_in[5];
    float* out = (float*)d_out;

    cudaFuncSetAttribute(k_gemm<M_XPROJ>,  cudaFuncAttributeMaxDynamicSharedMemorySize, SMEM_BYTES);
    cudaFuncSetAttribute(k_gemm<M_SCORES>, cudaFuncAttributeMaxDynamicSharedMemorySize, SMEM_BYTES);
    cudaFuncSetAttribute(k_gemm<M_AMODE>,  cudaFuncAttributeMaxDynamicSharedMemorySize, SMEM_BYTES);
    cudaFuncSetAttribute(k_gemm<M_YPROJ>,  cudaFuncAttributeMaxDynamicSharedMemorySize, SMEM_BYTES);
    cudaFuncSetAttribute(k_gemm<M_ENC>,    cudaFuncAttributeMaxDynamicSharedMemorySize, SMEM_BYTES);
    cudaFuncSetAttribute(k_gemm<M_RO>,     cudaFuncAttributeMaxDynamicSharedMemorySize, SMEM_BYTES);

    // launch order: 0 k_prep, 1 k_init_v, 2 xproj, 3 SCORES (ncu capture slot), ...
    k_prep<<<PREP_TOT, 256>>>(dx, dy, enc, ro);
    k_init_v<<<CB*CT/8, 256>>>(idx, wte);

    for (int l = 0; l < CL; l++){
        k_gemm<M_XPROJ> <<<dim3(CNH/128, CT/128, CB*CH), 256, SMEM_BYTES>>>(nullptr);
        k_gemm<M_SCORES><<<dim3(36,      1,      CB*CH), 256, SMEM_BYTES>>>(nullptr);
        k_gemm<M_AMODE> <<<dim3(CD/128,  CT/128, CB*CH), 256, SMEM_BYTES>>>(nullptr);
        k_lna<<<CB*CH*CT/8, 256>>>();
        k_gemm<M_YPROJ> <<<dim3(CNH/128, CT/128, CB*CH), 256, SMEM_BYTES>>>(nullptr);
        k_gemm<M_ENC>   <<<dim3(CD/128, (CB*CT)/128, 8), 256, SMEM_BYTES>>>(nullptr);
        k_post<<<CB*CT/8, 256>>>();
    }
    k_gemm<M_RO><<<dim3(CV/128, (CB*CT)/128, 1), 256, SMEM_BYTES>>>(out);
}

// round 15
// speedup vs baseline: 1.4272x; 1.0051x over previous
#include <cuda_runtime.h>
#include <cuda_fp16.h>
#include <math.h>
#include <stdint.h>

#define CB 2
#define CT 1024
#define CD 256
#define CH 4
#define CNH 8192
#define CN 32768
#define CV 256
#define CL 6
#define FH 4096
#define EPSV 1e-5f

// smem geometry: 4 arrays (Ah, Al, Bh, Bl), 128 rows x 64B (KC=32), XOR-swizzled
#define ARR_BYTES (128*64)             // 8192
#define STAGE_BYTES (4*ARR_BYTES)      // 32768
#define NSTAGE 3
#define SMEM_BYTES (NSTAGE*STAGE_BYTES) // 98304 -> 2 CTAs/SM

// ---------------- device scratch ----------------
__device__ __align__(256) float  g_v   [CB*CT*CD];
__device__ __align__(256) __half g_vh  [CB*CT*CD];
__device__ __align__(256) __half g_vl  [CB*CT*CD];
__device__ __align__(256) __half g_vTh [CB*CD*CT];
__device__ __align__(256) __half g_vTl [CB*CD*CT];
__device__ __align__(256) __half g_qh  [(size_t)CB*CH*CT*CNH];
__device__ __align__(256) __half g_ql  [(size_t)CB*CH*CT*CNH];
__device__ __align__(256) __half g_sh  [(size_t)CB*CH*CT*CT];   // zero-init; upper-tri stays 0
__device__ __align__(256) __half g_sl  [(size_t)CB*CH*CT*CT];
__device__ __align__(256) float  g_a   [CB*CH*CT*CD];
__device__ __align__(256) __half g_lah [CB*CH*CT*CD];
__device__ __align__(256) __half g_lal [CB*CH*CT*CD];
__device__ __align__(256) __half g_yh  [(size_t)CB*CT*CN];
__device__ __align__(256) __half g_yl  [(size_t)CB*CT*CN];
__device__ __align__(256) float  g_zp  [(size_t)8*CB*CT*CD];
__device__ __align__(256) float2 g_rope[(size_t)CT*FH];
// weights stored TRANSPOSED (K-major for B operand)
__device__ __align__(256) __half g_wxh [(size_t)CH*CD*CNH];
__device__ __align__(256) __half g_wxl [(size_t)CH*CD*CNH];
__device__ __align__(256) __half g_wyh [(size_t)CH*CD*CNH];
__device__ __align__(256) __half g_wyl [(size_t)CH*CD*CNH];
__device__ __align__(256) __half g_ench[(size_t)CN*CD];
__device__ __align__(256) __half g_encl[(size_t)CN*CD];
__device__ __align__(256) __half g_roh [CD*CV];
__device__ __align__(256) __half g_rol [CD*CV];

// ---------------- PTX helpers ----------------
__device__ __forceinline__ uint32_t smem_u32(const void* p){
    uint32_t a;
    asm("{ .reg .u64 t; cvta.to.shared.u64 t, %1; cvt.u32.u64 %0, t; }" : "=r"(a) : "l"(p));
    return a;
}
__device__ __forceinline__ void cpa16(uint32_t s, const void* g){
    asm volatile("cp.async.cg.shared.global [%0], [%1], 16;" :: "r"(s), "l"(g));
}
__device__ __forceinline__ void ldm4(uint32_t* r, uint32_t a){
    asm volatile("ldmatrix.sync.aligned.m8n8.x4.shared.b16 {%0,%1,%2,%3}, [%4];"
        : "=r"(r[0]), "=r"(r[1]), "=r"(r[2]), "=r"(r[3]) : "r"(a));
}
__device__ __forceinline__ void mma16816(float* d, const uint32_t* a, const uint32_t* b){
    asm volatile(
        "mma.sync.aligned.m16n8k16.row.col.f32.f16.f16.f32 "
        "{%0,%1,%2,%3}, {%4,%5,%6,%7}, {%8,%9}, {%0,%1,%2,%3};"
        : "+f"(d[0]), "+f"(d[1]), "+f"(d[2]), "+f"(d[3])
        : "r"(a[0]), "r"(a[1]), "r"(a[2]), "r"(a[3]), "r"(b[0]), "r"(b[1]));
}
// XOR-swizzled smem address: 64B rows, 4 x 16B chunks, chunk ^= (row>>1)&3
__device__ __forceinline__ uint32_t swadr(uint32_t row, uint32_t chunk){
    return (row << 6) + (((chunk ^ ((row >> 1) & 3u)) & 3u) << 4);
}

// ---------------- small helpers ----------------
__device__ __forceinline__ float wsum(float v){
#pragma unroll
    for (int o = 16; o > 0; o >>= 1) v += __shfl_xor_sync(0xffffffffu, v, o);
    return v;
}
__device__ __forceinline__ void split_store(__half* hi, __half* lo, size_t o, float v){
    __half h = __float2half(v);
    hi[o] = h;
    lo[o] = __float2half(v - __half2float(h));
}
__device__ __forceinline__ void split_pack(float v0, float v1, uint32_t& hi, uint32_t& lo){
    __half h0 = __float2half(v0), h1 = __float2half(v1);
    hi = (uint32_t)__half_as_ushort(h0) | ((uint32_t)__half_as_ushort(h1) << 16);
    __half l0 = __float2half(v0 - __half2float(h0));
    __half l1 = __float2half(v1 - __half2float(h1));
    lo = (uint32_t)__half_as_ushort(l0) | ((uint32_t)__half_as_ushort(l1) << 16);
}
__device__ __forceinline__ float unpack2sum(uint32_t hi, uint32_t lo, int which){
    unsigned short h = which ? (unsigned short)(hi >> 16) : (unsigned short)(hi & 0xffff);
    unsigned short l = which ? (unsigned short)(lo >> 16) : (unsigned short)(lo & 0xffff);
    return __half2float(__ushort_as_half(h)) + __half2float(__ushort_as_half(l));
}
// warp-per-row LN over 8 values/lane (256 cols)
__device__ __forceinline__ void warp_ln(float* v){
    float s = 0.f;
#pragma unroll
    for (int i = 0; i < 8; i++) s += v[i];
    float m = wsum(s) * (1.f/CD);
    float q = 0.f;
#pragma unroll
    for (int i = 0; i < 8; i++){ v[i] -= m; q += v[i]*v[i]; }
    float r = rsqrtf(wsum(q) * (1.f/CD) + EPSV);
#pragma unroll
    for (int i = 0; i < 8; i++) v[i] *= r;
}

// ---------------- merged prep kernel (tables + splitW + splitE) ----------------
// grid layout (1-D): [0,4096) tables | [4096,20480) splitW | [20480,28736) splitE
#define PREP_TAB  4096
#define PREP_W    (PREP_TAB + 16384)
#define PREP_TOT  (PREP_W + 8256)

__global__ void k_prep(const float* __restrict__ dx, const float* __restrict__ dy,
                       const float* __restrict__ enc, const float* __restrict__ ro){
    int bid = blockIdx.x;
    int tid = threadIdx.x;
    if (bid < PREP_TAB){
        int i = bid;
        double ex  = (2.0 * (double)i) / (double)CNH;
        double inv = exp(-ex * 9.210340371976184);
        for (int t = tid; t < CT; t += 256){
            double ang = (double)t * inv;
            double k = rint(ang * 0.15915494309189535);
            float red = (float)(ang - k * 6.283185307179586);
            float s, c;
            sincosf(red, &s, &c);
            g_rope[(size_t)t*FH + i] = make_float2(c, s);
        }
        return;
    }
    __shared__ float tile[32][33];
    int tx = tid & 31, ty = tid >> 5;
    const float* s;
    __half *hi, *lo;
    int R, C, c0, r0;
    if (bid < PREP_W){
        int w = bid - PREP_TAB;
        int z = w >> 11;
        int rem = w & 2047;
        int cx = rem & 255;
        int cy = rem >> 8;
        if (z < 4){ s = dx + (size_t)z*CD*CNH;     hi = g_wxh + (size_t)z*CD*CNH;     lo = g_wxl + (size_t)z*CD*CNH; }
        else      { s = dy + (size_t)(z-4)*CD*CNH; hi = g_wyh + (size_t)(z-4)*CD*CNH; lo = g_wyl + (size_t)(z-4)*CD*CNH; }
        R = CD; C = CNH; c0 = cx*32; r0 = cy*32;
    } else {
        int e = bid - PREP_W;            // 0..8255
        int cx = e & 7;
        int gy = e >> 3;                 // 0..1031
        if (gy < CN/32){ s = enc; hi = g_ench; lo = g_encl; R = CN; C = CD; }
        else           { s = ro;  hi = g_roh;  lo = g_rol;  R = CD; C = CV; gy -= CN/32; }
        c0 = cx*32; r0 = gy*32;
    }
    for (int i = ty; i < 32; i += 8)
        tile[i][tx] = s[(size_t)(r0+i)*C + c0 + tx];
    __syncthreads();
    for (int i = ty; i < 32; i += 8){
        float v = tile[tx][i];
        __half hh = __float2half(v);
        size_t o = (size_t)(c0+i)*R + r0 + tx;
        hi[o] = hh;
        lo[o] = __float2half(v - __half2float(hh));
    }
}

// warp-per-row: v = ln(wte[idx])
__global__ void k_init_v(const int* __restrict__ idx, const float* __restrict__ wte){
    int gw = (blockIdx.x*256 + threadIdx.x) >> 5;
    int lane = threadIdx.x & 31;
    int b = gw >> 10, t = gw & 1023;
    const float4* src = (const float4*)(wte + (size_t)idx[gw]*CD);
    float4 x0 = src[lane], x1 = src[lane + 32];
    float v[8] = {x0.x, x0.y, x0.z, x0.w, x1.x, x1.y, x1.z, x1.w};
    warp_ln(v);
    size_t rowoff = (size_t)gw*CD;
    ((float4*)(g_v + rowoff))[lane]      = make_float4(v[0], v[1], v[2], v[3]);
    ((float4*)(g_v + rowoff))[lane + 32] = make_float4(v[4], v[5], v[6], v[7]);
#pragma unroll
    for (int half4 = 0; half4 < 2; half4++){
        int d0 = half4*128 + lane*4;
#pragma unroll
        for (int j = 0; j < 4; j += 2){
            uint32_t hi, lo;
            split_pack(v[half4*4 + j], v[half4*4 + j + 1], hi, lo);
            *(uint32_t*)(g_vh + rowoff + d0 + j) = hi;
            *(uint32_t*)(g_vl + rowoff + d0 + j) = lo;
        }
#pragma unroll
        for (int j = 0; j < 4; j++){
            int d = d0 + j;
            split_store(g_vTh, g_vTl, ((size_t)b*CD + d)*CT + t, v[half4*4 + j]);
        }
    }
}

// warp-per-row: ln(a) -> lah/lal
__global__ void k_lna(){
    int gw = (blockIdx.x*256 + threadIdx.x) >> 5;
    int lane = threadIdx.x & 31;
    size_t rowoff = (size_t)gw*CD;
    const float4* src = (const float4*)(g_a + rowoff);
    float4 x0 = src[lane], x1 = src[lane + 32];
    float v[8] = {x0.x, x0.y, x0.z, x0.w, x1.x, x1.y, x1.z, x1.w};
    warp_ln(v);
#pragma unroll
    for (int half4 = 0; half4 < 2; half4++){
        int d0 = half4*128 + lane*4;
#pragma unroll
        for (int j = 0; j < 4; j += 2){
            uint32_t hi, lo;
            split_pack(v[half4*4 + j], v[half4*4 + j + 1], hi, lo);
            *(uint32_t*)(g_lah + rowoff + d0 + j) = hi;
            *(uint32_t*)(g_lal + rowoff + d0 + j) = lo;
        }
    }
}

// warp-per-row: z = sum partials; v = ln(v + ln(z))
__global__ void k_post(){
    int gw = (blockIdx.x*256 + threadIdx.x) >> 5;
    int lane = threadIdx.x & 31;
    int b = gw >> 10, t = gw & 1023;
    size_t rowoff = (size_t)gw*CD;
    float z[8] = {0,0,0,0,0,0,0,0};
#pragma unroll
    for (int p = 0; p < 8; p++){
        const float4* zp = (const float4*)(g_zp + (size_t)p*CB*CT*CD + rowoff);
        float4 a0 = zp[lane], a1 = zp[lane + 32];
        z[0] += a0.x; z[1] += a0.y; z[2] += a0.z; z[3] += a0.w;
        z[4] += a1.x; z[5] += a1.y; z[6] += a1.z; z[7] += a1.w;
    }
    warp_ln(z);
    const float4* vs = (const float4*)(g_v + rowoff);
    float4 v0 = vs[lane], v1 = vs[lane + 32];
    float u[8] = {v0.x + z[0], v0.y + z[1], v0.z + z[2], v0.w + z[3],
                  v1.x + z[4], v1.y + z[5], v1.z + z[6], v1.w + z[7]};
    warp_ln(u);
    ((float4*)(g_v + rowoff))[lane]      = make_float4(u[0], u[1], u[2], u[3]);
    ((float4*)(g_v + rowoff))[lane + 32] = make_float4(u[4], u[5], u[6], u[7]);
#pragma unroll
    for (int half4 = 0; half4 < 2; half4++){
        int d0 = half4*128 + lane*4;
#pragma unroll
        for (int j = 0; j < 4; j += 2){
            uint32_t hi, lo;
            split_pack(u[half4*4 + j], u[half4*4 + j + 1], hi, lo);
            *(uint32_t*)(g_vh + rowoff + d0 + j) = hi;
            *(uint32_t*)(g_vl + rowoff + d0 + j) = lo;
        }
#pragma unroll
        for (int j = 0; j < 4; j++){
            int d = d0 + j;
            split_store(g_vTh, g_vTl, ((size_t)b*CD + d)*CT + t, u[half4*4 + j]);
        }
    }
}

// ---------------- unified split-fp16 mma.sync GEMM ----------------
#define M_XPROJ  0
#define M_SCORES 1
#define M_AMODE  2
#define M_YPROJ  3
#define M_ENC    4
#define M_RO     5

template<int MODE>
__global__ void __launch_bounds__(256, 2) k_gemm(float* out_arg){
    extern __shared__ __align__(128) char dyn[];
    uint32_t smb = smem_u32(dyn);

    // static weight operand B: drop the Ah*Bl residual term (2-term split)
    constexpr bool DROPBL = (MODE == M_XPROJ || MODE == M_YPROJ ||
                             MODE == M_ENC   || MODE == M_RO);

    int tid  = threadIdx.x;
    int warp = tid >> 5, lane = tid & 31;
    int wr = warp >> 1, wc = warp & 1;          // warp tile: rows wr*32, cols wc*64

    int bh = blockIdx.z, b = bh >> 2, h = bh & 3;
    const __half *Ah, *Al, *Bh, *Bl;
    size_t lda, ldb;
    int m0, n0, Klen;
    bool shareB = false;

    if (MODE == M_XPROJ){
        Ah = g_vh + (size_t)b*CT*CD;   Al = g_vl + (size_t)b*CT*CD;   lda = CD;
        Bh = g_wxh + (size_t)h*CD*CNH; Bl = g_wxl + (size_t)h*CD*CNH; ldb = CD;
        m0 = blockIdx.y*128; n0 = blockIdx.x*128; Klen = CD;
    } else if (MODE == M_YPROJ){
        Ah = g_lah + (size_t)bh*CT*CD; Al = g_lal + (size_t)bh*CT*CD; lda = CD;
        Bh = g_wyh + (size_t)h*CD*CNH; Bl = g_wyl + (size_t)h*CD*CNH; ldb = CD;
        m0 = blockIdx.y*128; n0 = blockIdx.x*128; Klen = CD;
    } else if (MODE == M_SCORES){
        int p = blockIdx.x, tT = 0, acc0 = 0;
        while (acc0 + tT + 1 <= p){ tT++; acc0 += tT; }
        int sT = p - acc0;
        Ah = g_qh + (size_t)bh*CT*CNH; Al = g_ql + (size_t)bh*CT*CNH; lda = CNH;
        Bh = Ah; Bl = Al; ldb = CNH;
        m0 = tT*128; n0 = sT*128; Klen = CNH;
        shareB = (tT == sT);
    } else if (MODE == M_AMODE){
        Ah = g_sh + (size_t)bh*CT*CT;  Al = g_sl + (size_t)bh*CT*CT;  lda = CT;
        Bh = g_vTh + (size_t)b*CD*CT;  Bl = g_vTl + (size_t)b*CD*CT;  ldb = CT;
        m0 = blockIdx.y*128; n0 = blockIdx.x*128;
        Klen = (blockIdx.y + 1) * 128;                // causal K clamp
    } else if (MODE == M_ENC){
        int z = blockIdx.z;
        Ah = g_yh + (size_t)z*4096;   Al = g_yl + (size_t)z*4096;   lda = CN;
        Bh = g_ench + (size_t)z*4096; Bl = g_encl + (size_t)z*4096; ldb = CN;
        m0 = blockIdx.y*128; n0 = blockIdx.x*128; Klen = 4096;
    } else { // M_RO
        Ah = g_vh; Al = g_vl; lda = CD;
        Bh = g_roh; Bl = g_rol; ldb = CD;
        m0 = blockIdx.y*128; n0 = blockIdx.x*128; Klen = CD;
    }

    float acc[2][8][4];
#pragma unroll
    for (int i = 0; i < 2; i++)
#pragma unroll
        for (int j = 0; j < 8; j++)
#pragma unroll
            for (int q = 0; q < 4; q++) acc[i][j][q] = 0.f;

    const int nch = Klen >> 5;   // KC = 32 halves per chunk

    // ---- async stage issuer: up to 4 arrays x 128 rows x 4 x 16B (swizzled) ----
    auto issue = [&](int c){
        uint32_t sbase = smb + (uint32_t)(c % NSTAGE) * STAGE_BYTES;
        int kb = c << 5;
        uint32_t kc = tid & 3;         // 16B chunk in 64B row
        int rlo = tid >> 2;            // 0..63
        int nArr = shareB ? 2 : (DROPBL ? 3 : 4);
#pragma unroll
        for (int it = 0; it < 8; it++){
            int arr = it >> 1;                       // 0=Ah 1=Al 2=Bh 3=Bl
            if (arr >= nArr) break;
            uint32_t r = (uint32_t)(((it & 1) << 6) + rlo);  // 0..127
            const __half* gp = (arr == 0) ? Ah : (arr == 1) ? Al : (arr == 2) ? Bh : Bl;
            size_t ld  = (arr < 2) ? lda : ldb;
            int    off = (arr < 2) ? m0  : n0;
            cpa16(sbase + (uint32_t)arr*ARR_BYTES + swadr(r, kc),
                  gp + ((size_t)(off + (int)r))*ld + kb + kc*8);
        }
        asm volatile("cp.async.commit_group;" ::: "memory");
    };

    issue(0);
    issue(1);
    for (int c = 0; c < nch; c++){
        if (c + 1 < nch) asm volatile("cp.async.wait_group 1;" ::: "memory");
        else             asm volatile("cp.async.wait_group 0;" ::: "memory");
        __syncthreads();          // single barrier per chunk
        if (c + 2 < nch) issue(c + 2);

        uint32_t sbase = smb + (uint32_t)(c % NSTAGE) * STAGE_BYTES;
        uint32_t sAh = sbase, sAl = sbase + ARR_BYTES;
        uint32_t sBh = shareB ? sAh : (sbase + 2*ARR_BYTES);
        uint32_t sBl = shareB ? sAl : (sbase + 3*ARR_BYTES);

#pragma unroll
        for (int k16 = 0; k16 < 2; k16++){
            uint32_t aH[2][4], aL[2][4];
#pragma unroll
            for (int mi = 0; mi < 2; mi++){
                uint32_t row = (uint32_t)(wr*32 + mi*16 + (lane & 15));
                uint32_t ck  = (uint32_t)(k16*2 + (lane >> 4));
                uint32_t ro  = swadr(row, ck);
                ldm4(aH[mi], sAh + ro);
                ldm4(aL[mi], sAl + ro);
            }
#pragma unroll
            for (int nj2 = 0; nj2 < 4; nj2++){
                uint32_t row = (uint32_t)(wc*64 + nj2*16 + (lane & 7) + ((lane >> 4) & 1)*8);
                uint32_t ck  = (uint32_t)(k16*2 + ((lane >> 3) & 1));
                uint32_t ro  = swadr(row, ck);
                uint32_t bh4[4];
                ldm4(bh4, sBh + ro);
                if (DROPBL){
#pragma unroll
                    for (int mi = 0; mi < 2; mi++){
                        mma16816(acc[mi][nj2*2],     aH[mi], bh4);
                        mma16816(acc[mi][nj2*2],     aL[mi], bh4);
                        mma16816(acc[mi][nj2*2 + 1], aH[mi], bh4 + 2);
                        mma16816(acc[mi][nj2*2 + 1], aL[mi], bh4 + 2);
                    }
                } else {
                    uint32_t bl4[4];
                    ldm4(bl4, sBl + ro);
#pragma unroll
                    for (int mi = 0; mi < 2; mi++){
                        mma16816(acc[mi][nj2*2],     aH[mi], bh4);
                        mma16816(acc[mi][nj2*2],     aH[mi], bl4);
                        mma16816(acc[mi][nj2*2],     aL[mi], bh4);
                        mma16816(acc[mi][nj2*2 + 1], aH[mi], bh4 + 2);
                        mma16816(acc[mi][nj2*2 + 1], aH[mi], bl4 + 2);
                        mma16816(acc[mi][nj2*2 + 1], aL[mi], bh4 + 2);
                    }
                }
            }
        }
    }

    // ---------------- epilogue: direct from accumulators ----------------
#pragma unroll
    for (int mi = 0; mi < 2; mi++){
#pragma unroll
        for (int nj = 0; nj < 8; nj++){
            int rb = wr*32 + mi*16 + (lane >> 2);
            int cb = wc*64 + nj*8 + ((lane & 3) << 1);
#pragma unroll
            for (int hrow = 0; hrow < 2; hrow++){
                int r = rb + hrow*8;
                float v0 = acc[mi][nj][hrow*2];
                float v1 = acc[mi][nj][hrow*2 + 1];
                int t = m0 + r;

                if (MODE == M_SCORES){
                    int s = n0 + cb;
                    if (s >= t) continue;              // masked pair: region persistently 0
                    if (s + 1 >= t) v1 = 0.f;
                    uint32_t hi, lo;
                    split_pack(v0, v1, hi, lo);
                    size_t o = (size_t)bh*CT*CT + (size_t)t*CT + s;
                    *(uint32_t*)(g_sh + o) = hi;
                    *(uint32_t*)(g_sl + o) = lo;
                } else if (MODE == M_XPROJ){
                    int n = n0 + cb;
                    float x1 = fmaxf(v0, 0.f), x2 = fmaxf(v1, 0.f);
                    size_t xi = (size_t)bh*CT*CNH + (size_t)t*CNH + n;
                    float2 cs2 = g_rope[(size_t)t*FH + (n >> 1)];
                    float q1 = x1*cs2.x - x2*cs2.y;
                    float q2 = x1*cs2.y + x2*cs2.x;
                    uint32_t hi, lo;
                    split_pack(q1, q2, hi, lo);
                    *(uint32_t*)(g_qh + xi) = hi;
                    *(uint32_t*)(g_ql + xi) = lo;
                } else if (MODE == M_YPROJ){
                    int n = n0 + cb;
                    size_t xi = (size_t)bh*CT*CNH + (size_t)t*CNH + n;
                    // reconstruct x = R^-1(q) from split-fp16 q (rope is a rotation)
                    uint32_t qh2 = *(const uint32_t*)(g_qh + xi);
                    uint32_t ql2 = *(const uint32_t*)(g_ql + xi);
                    float q1 = unpack2sum(qh2, ql2, 0);
                    float q2 = unpack2sum(qh2, ql2, 1);
                    float2 cs2 = g_rope[(size_t)t*FH + (n >> 1)];
                    float xv1 = fmaxf(q1*cs2.x + q2*cs2.y, 0.f);
                    float xv2 = fmaxf(q2*cs2.x - q1*cs2.y, 0.f);
                    float y1 = fmaxf(v0, 0.f) * xv1;
                    float y2 = fmaxf(v1, 0.f) * xv2;
                    uint32_t hi, lo;
                    split_pack(y1, y2, hi, lo);
                    size_t yi = ((size_t)b*CT + t)*CN + (size_t)h*CNH + n;
                    *(uint32_t*)(g_yh + yi) = hi;
                    *(uint32_t*)(g_yl + yi) = lo;
                } else {
                    float* op; size_t ldo;
                    if (MODE == M_AMODE){ op = g_a + (size_t)bh*CT*CD; ldo = CD; }
                    else if (MODE == M_ENC){ op = g_zp + (size_t)blockIdx.z*CB*CT*CD; ldo = CD; }
                    else { op = out_arg; ldo = CV; }
                    *(float2*)(op + (size_t)t*ldo + n0 + cb) = make_float2(v0, v1);
                }
            }
        }
    }
}

// ---------------- launch ----------------
extern "C" void kernel_launch(void* const* d_in, const int* in_sizes, int n_in,
                              void* d_out, int out_size){
    const int*   idx = (const int*)  d_in[0];
    const float* wte = (const float*)d_in[1];
    const float* enc = (const float*)d_in[2];
    const float* dx  = (const float*)d_in[3];
    const float* dy  = (const float*)d_in[4];
    const float* ro  = (const float*)d_in[5];
    float* out = (float*)d_out;

    cudaFuncSetAttribute(k_gemm<M_XPROJ>,  cudaFuncAttributeMaxDynamicSharedMemorySize, SMEM_BYTES);
    cudaFuncSetAttribute(k_gemm<M_SCORES>, cudaFuncAttributeMaxDynamicSharedMemorySize, SMEM_BYTES);
    cudaFuncSetAttribute(k_gemm<M_AMODE>,  cudaFuncAttributeMaxDynamicSharedMemorySize, SMEM_BYTES);
    cudaFuncSetAttribute(k_gemm<M_YPROJ>,  cudaFuncAttributeMaxDynamicSharedMemorySize, SMEM_BYTES);
    cudaFuncSetAttribute(k_gemm<M_ENC>,    cudaFuncAttributeMaxDynamicSharedMemorySize, SMEM_BYTES);
    cudaFuncSetAttribute(k_gemm<M_RO>,     cudaFuncAttributeMaxDynamicSharedMemorySize, SMEM_BYTES);

    // launch order: 0 k_prep, 1 k_init_v, 2 xproj, 3 SCORES (ncu capture slot), ...
    k_prep<<<PREP_TOT, 256>>>(dx, dy, enc, ro);
    k_init_v<<<CB*CT/8, 256>>>(idx, wte);

    for (int l = 0; l < CL; l++){
        k_gemm<M_XPROJ> <<<dim3(CNH/128, CT/128, CB*CH), 256, SMEM_BYTES>>>(nullptr);
        k_gemm<M_SCORES><<<dim3(36,      1,      CB*CH), 256, SMEM_BYTES>>>(nullptr);
        k_gemm<M_AMODE> <<<dim3(CD/128,  CT/128, CB*CH), 256, SMEM_BYTES>>>(nullptr);
        k_lna<<<CB*CH*CT/8, 256>>>();
        k_gemm<M_YPROJ> <<<dim3(CNH/128, CT/128, CB*CH), 256, SMEM_BYTES>>>(nullptr);
        k_gemm<M_ENC>   <<<dim3(CD/128, (CB*CT)/128, 8), 256, SMEM_BYTES>>>(nullptr);
        k_post<<<CB*CT/8, 256>>>();
    }
    k_gemm<M_RO><<<dim3(CV/128, (CB*CT)/128, 1), 256, SMEM_BYTES>>>(out);
}